// round 10
// baseline (speedup 1.0000x reference)
#include <cuda_runtime.h>
#include <math.h>

// Problem constants
#define PP 20
#define NN 1024
#define DD 512
#define TPB 128          // thread t owns d-values [4t, 4t+3]
#define NWARP (TPB / 32)
#define NS 8             // atomic slot count (contention reduction)
#define EPS 1e-8f

// Persistent accumulators. Zero at module load; the LAST block re-zeroes them
// after consuming, so every graph replay starts from zeros deterministically.
__device__ float gS[NS][DD];      // slot-partial of S[d] = sum_n an[n][d]
__device__ float gT[NS][DD];      // slot-partial of T[d] = sum_{p,n} zn[p][n][d]
__device__ float gDiag[NS];       // slot-partial of sum_n (sum_p zn_p) . an
__device__ unsigned int gTicket;  // completed-block counter (reset by last block)

// One block per column n. Phase 2 re-reads global memory (L2-resident:
// whole input 40MB < L2). __launch_bounds__(128, 8) caps regs at 64 so the
// once-per-launch finale path cannot wreck occupancy of the streaming path.
__global__ __launch_bounds__(TPB, 8) void fused_kernel(const float* __restrict__ z,
                                                       float* __restrict__ out) {
    const int n    = blockIdx.x;
    const int t    = threadIdx.x;
    const int wid  = t >> 5;
    const int lane = t & 31;
    const int slot = n & (NS - 1);
    const int d0   = t * 4;

    __shared__ float wp[NWARP][21];
    __shared__ float inv[21];      // [p]=1/max(||z_p||,eps), [20]=avg
    __shared__ float wdg[NWARP];
    __shared__ unsigned int ticket_s;

    const size_t stride = (size_t)NN * DD / 4;   // float4 stride between patches
    const float4* base =
        reinterpret_cast<const float4*>(z) + (size_t)n * (DD / 4) + t;

    // ---- phase 1: avg + norm partials (20 independent LDG.128 in flight) ----
    float4 avg = make_float4(0.f, 0.f, 0.f, 0.f);
    float s[21];
    #pragma unroll
    for (int p = 0; p < PP; ++p) {
        float4 v = base[(size_t)p * stride];
        avg.x += v.x; avg.y += v.y; avg.z += v.z; avg.w += v.w;
        s[p] = v.x * v.x + v.y * v.y + v.z * v.z + v.w * v.w;
    }
    const float invP = 1.0f / (float)PP;
    avg.x *= invP; avg.y *= invP; avg.z *= invP; avg.w *= invP;
    s[20] = avg.x * avg.x + avg.y * avg.y + avg.z * avg.z + avg.w * avg.w;

    // ---- block-reduce the 21 sums ----
    #pragma unroll
    for (int i = 0; i < 21; ++i) {
        float v = s[i];
        #pragma unroll
        for (int o = 16; o > 0; o >>= 1)
            v += __shfl_xor_sync(0xffffffffu, v, o);
        s[i] = v;
    }
    if (lane == 0) {
        #pragma unroll
        for (int i = 0; i < 21; ++i) wp[wid][i] = s[i];
    }
    __syncthreads();
    if (t < 21) {
        float v = 0.f;
        #pragma unroll
        for (int w = 0; w < NWARP; ++w) v += wp[w][t];
        inv[t] = 1.0f / fmaxf(sqrtf(v), EPS);
    }
    __syncthreads();

    // ---- phase 2: reload rows (L2 hit) -> zn ----
    float4 zn = make_float4(0.f, 0.f, 0.f, 0.f);
    #pragma unroll
    for (int p = 0; p < PP; ++p) {
        float4 v = base[(size_t)p * stride];
        const float ip = inv[p];
        zn.x += v.x * ip; zn.y += v.y * ip;
        zn.z += v.z * ip; zn.w += v.w * ip;
    }

    const float inv_avg = inv[20];
    const float an0 = avg.x * inv_avg, an1 = avg.y * inv_avg;
    const float an2 = avg.z * inv_avg, an3 = avg.w * inv_avg;

    // diag_n partial: zn . an
    float dsum = zn.x * an0 + zn.y * an1 + zn.z * an2 + zn.w * an3;
    #pragma unroll
    for (int o = 16; o > 0; o >>= 1)
        dsum += __shfl_xor_sync(0xffffffffu, dsum, o);
    if (lane == 0) wdg[wid] = dsum;

    // slotted global accumulation (128 updates per address)
    atomicAdd(&gS[slot][d0 + 0], an0);
    atomicAdd(&gS[slot][d0 + 1], an1);
    atomicAdd(&gS[slot][d0 + 2], an2);
    atomicAdd(&gS[slot][d0 + 3], an3);
    atomicAdd(&gT[slot][d0 + 0], zn.x);
    atomicAdd(&gT[slot][d0 + 1], zn.y);
    atomicAdd(&gT[slot][d0 + 2], zn.z);
    atomicAdd(&gT[slot][d0 + 3], zn.w);

    __syncthreads();
    if (t == 0) {
        float dg = 0.f;
        #pragma unroll
        for (int w = 0; w < NWARP; ++w) dg += wdg[w];
        atomicAdd(&gDiag[slot], dg);
    }

    // ---- completion ticket (threadFenceReduction pattern) ----
    __threadfence();
    __syncthreads();
    if (t == 0) ticket_s = atomicAdd(&gTicket, 1u);
    __syncthreads();
    if (ticket_s != NN - 1) return;

    // ======== LAST BLOCK (runs once): final scalar + state reset ========
    // #pragma unroll 1 keeps this cold path's register demand minimal so it
    // doesn't inflate the whole kernel's allocation under the 64-reg cap.
    float v = 0.f;
    #pragma unroll 1
    for (int j = 0; j < 4; ++j) {
        const int d = d0 + j;
        float S = 0.f, T = 0.f;
        #pragma unroll 1
        for (int sl = 0; sl < NS; ++sl) { S += gS[sl][d]; T += gT[sl][d]; }
        v += S * T;
    }
    #pragma unroll
    for (int o = 16; o > 0; o >>= 1)
        v += __shfl_xor_sync(0xffffffffu, v, o);
    if (lane == 0) wdg[wid] = v;          // reuse wdg for T.S partials

    float dg_all = 0.f;
    if (t == 0) {
        #pragma unroll 1
        for (int sl = 0; sl < NS; ++sl) dg_all += gDiag[sl];
    }
    __syncthreads();

    if (t == 0) {
        float ts = 0.f;
        #pragma unroll
        for (int w = 0; w < NWARP; ++w) ts += wdg[w];
        const double count = 20.0 * 1024.0 * 1023.0;
        out[0] = (float)(((double)ts - (double)dg_all) / count - 1.0);
    }

    // re-zero persistent state for the next graph replay
    #pragma unroll 1
    for (int sl = 0; sl < NS; ++sl) {
        #pragma unroll
        for (int j = 0; j < 4; ++j) {
            gS[sl][d0 + j] = 0.f;
            gT[sl][d0 + j] = 0.f;
        }
    }
    if (t < NS) gDiag[t] = 0.f;
    if (t == 0) gTicket = 0u;
}

extern "C" void kernel_launch(void* const* d_in, const int* in_sizes, int n_in,
                              void* d_out, int out_size) {
    const float* z_list = (const float*)d_in[0];
    // d_in[1] (z_avg) ignored — reference recomputes it from z_list.
    (void)in_sizes; (void)n_in; (void)out_size;
    float* out = (float*)d_out;

    fused_kernel<<<NN, TPB>>>(z_list, out);
}

// round 11
// speedup vs baseline: 1.2798x; 1.2798x over previous
#include <cuda_runtime.h>
#include <math.h>

// Problem constants
#define PP 20
#define NN 1024
#define DD 512
#define TPB 512          // one thread per d-value: tile fits in 20 registers
#define NWARP (TPB / 32) // 16
#define NS 8             // atomic slot count (contention reduction)
#define EPS 1e-8f

// Persistent accumulators. Zero at module load; the LAST block re-zeroes them
// after consuming, so every graph replay starts from zeros deterministically.
__device__ float gS[NS][DD];      // slot-partial of S[d] = sum_n an[n][d]
__device__ float gT[NS][DD];      // slot-partial of T[d] = sum_{p,n} zn[p][n][d]
__device__ float gDiag[NS];       // slot-partial of sum_n (sum_p zn_p) . an
__device__ unsigned int gTicket;  // completed-block counter (reset by last block)

// One block per column n; thread t owns scalar d = t. The 20-row tile lives
// in 20 registers, so the input is read from DRAM exactly ONCE (no phase-2
// reload, no smem tile). Norm partials are warp-reduced in-loop so no wide
// live array exists. Ticketed last block computes the final scalar & resets.
__global__ __launch_bounds__(TPB) void fused_kernel(const float* __restrict__ z,
                                                    float* __restrict__ out) {
    const int n    = blockIdx.x;
    const int t    = threadIdx.x;
    const int wid  = t >> 5;
    const int lane = t & 31;
    const int slot = n & (NS - 1);

    __shared__ float wp[NWARP][21];
    __shared__ float inv[21];      // [p]=1/max(||z_p||,eps), [20]=avg
    __shared__ float wdg[NWARP];
    __shared__ unsigned int ticket_s;

    const size_t stride = (size_t)NN * DD;   // floats between patches
    const float* base = z + (size_t)n * DD + t;

    // ---- single DRAM pass: 20 independent coalesced LDG.32 ----
    float tile[PP];
    float avg = 0.f;
    #pragma unroll
    for (int p = 0; p < PP; ++p) {
        tile[p] = base[(size_t)p * stride];
        avg += tile[p];
    }
    avg *= (1.0f / (float)PP);

    // ---- norm partials, warp-reduced in-loop (no wide live array) ----
    #pragma unroll
    for (int p = 0; p < PP; ++p) {
        float v = tile[p] * tile[p];
        #pragma unroll
        for (int o = 16; o > 0; o >>= 1)
            v += __shfl_xor_sync(0xffffffffu, v, o);
        if (lane == 0) wp[wid][p] = v;
    }
    {
        float v = avg * avg;
        #pragma unroll
        for (int o = 16; o > 0; o >>= 1)
            v += __shfl_xor_sync(0xffffffffu, v, o);
        if (lane == 0) wp[wid][20] = v;
    }
    __syncthreads();
    if (t < 21) {
        float v = 0.f;
        #pragma unroll
        for (int w = 0; w < NWARP; ++w) v += wp[w][t];
        inv[t] = 1.0f / fmaxf(sqrtf(v), EPS);
    }
    __syncthreads();

    // ---- zn from the register tile ----
    float zn = 0.f;
    #pragma unroll
    for (int p = 0; p < PP; ++p)
        zn += tile[p] * inv[p];

    const float an = avg * inv[20];

    // diag_n partial: zn * an, block-reduced
    float dsum = zn * an;
    #pragma unroll
    for (int o = 16; o > 0; o >>= 1)
        dsum += __shfl_xor_sync(0xffffffffu, dsum, o);
    if (lane == 0) wdg[wid] = dsum;

    // slotted global accumulation (128 updates per address)
    atomicAdd(&gS[slot][t], an);
    atomicAdd(&gT[slot][t], zn);

    __syncthreads();
    if (t == 0) {
        float dg = 0.f;
        #pragma unroll
        for (int w = 0; w < NWARP; ++w) dg += wdg[w];
        atomicAdd(&gDiag[slot], dg);
    }

    // ---- completion ticket (threadFenceReduction pattern) ----
    __threadfence();
    __syncthreads();
    if (t == 0) ticket_s = atomicAdd(&gTicket, 1u);
    __syncthreads();
    if (ticket_s != NN - 1) return;

    // ======== LAST BLOCK (runs once): final scalar + state reset ========
    // unroll 1: keep this cold path register-light.
    float S = 0.f, T = 0.f;
    #pragma unroll 1
    for (int sl = 0; sl < NS; ++sl) { S += gS[sl][t]; T += gT[sl][t]; }
    float v = S * T;
    #pragma unroll
    for (int o = 16; o > 0; o >>= 1)
        v += __shfl_xor_sync(0xffffffffu, v, o);
    if (lane == 0) wdg[wid] = v;          // reuse wdg for T.S partials

    float dg_all = 0.f;
    if (t == 0) {
        #pragma unroll 1
        for (int sl = 0; sl < NS; ++sl) dg_all += gDiag[sl];
    }
    __syncthreads();

    if (t == 0) {
        float ts = 0.f;
        #pragma unroll
        for (int w = 0; w < NWARP; ++w) ts += wdg[w];
        const double count = 20.0 * 1024.0 * 1023.0;
        out[0] = (float)(((double)ts - (double)dg_all) / count - 1.0);
    }

    // re-zero persistent state for the next graph replay
    #pragma unroll 1
    for (int sl = 0; sl < NS; ++sl) { gS[sl][t] = 0.f; gT[sl][t] = 0.f; }
    if (t < NS) gDiag[t] = 0.f;
    if (t == 0) gTicket = 0u;
}

extern "C" void kernel_launch(void* const* d_in, const int* in_sizes, int n_in,
                              void* d_out, int out_size) {
    const float* z_list = (const float*)d_in[0];
    // d_in[1] (z_avg) ignored — reference recomputes it from z_list.
    (void)in_sizes; (void)n_in; (void)out_size;
    float* out = (float*)d_out;

    fused_kernel<<<NN, TPB>>>(z_list, out);
}

// round 12
// speedup vs baseline: 1.4056x; 1.0983x over previous
#include <cuda_runtime.h>
#include <math.h>

// Problem constants
#define PP 20
#define NN 1024
#define DD 512
#define TPB 640            // 20 warps: warp p owns row (p, n)
#define NWARP_R 16         // warps participating in d-phase (512 threads)
#define ROWF4 130          // row stride in float4 (128 data + 2 pad)
#define ROWF (ROWF4 * 4)   // 520 floats
#define NS 8               // atomic slot count
#define EPS 1e-8f

// Persistent accumulators. Zero at module load; the LAST block re-zeroes them
// after consuming, so every graph replay starts from zeros deterministically.
__device__ float gS[NS][DD];      // slot-partial of S[d] = sum_n an[n][d]
__device__ float gT[NS][DD];      // slot-partial of T[d] = sum_{p,n} zn[p][n][d]
__device__ float gDiag[NS];       // slot-partial of sum_n (sum_p zn_p) . an
__device__ unsigned int gTicket;  // completed-block counter (reset by last block)

// Block per column n, 20 warps.
// Phase A (warp-per-row): warp p streams row (p,n) with 4 LDG.128/lane,
//   stages it to smem, and computes ||z_p|| with ONE warp reduction.
//   All 20 norm reductions run in parallel across warps.
// Phase B (thread-per-d, t<512): one smem pass builds avg AND zn together
//   (inv[p] already known). Only 2 block-wide reductions remain:
//   ||avg||^2 and diag = zn . an.
// Ticketed last block computes the final scalar and resets state.
__global__ __launch_bounds__(TPB) void fused_kernel(const float* __restrict__ z,
                                                    float* __restrict__ out) {
    const int n    = blockIdx.x;
    const int t    = threadIdx.x;
    const int wid  = t >> 5;
    const int lane = t & 31;
    const int slot = n & (NS - 1);

    __shared__ float4 tile4[PP][ROWF4];      // 41.6 KB staged tile
    __shared__ float  inv_s[21];             // [p]=1/max(||z_p||,eps), [20]=avg
    __shared__ float  wp[NWARP_R];           // avg^2 partials
    __shared__ float  wdg[NWARP_R];          // diag partials
    __shared__ unsigned int ticket_s;

    float* tilef = reinterpret_cast<float*>(tile4);

    // ---- Phase A: warp wid loads row (wid, n); norm via one warp reduce ----
    {
        const float4* rowg = reinterpret_cast<const float4*>(
            z + ((size_t)wid * NN + (size_t)n) * DD);
        float ssq = 0.f;
        #pragma unroll
        for (int k = 0; k < 4; ++k) {
            float4 v = rowg[k * 32 + lane];
            tile4[wid][k * 32 + lane] = v;
            ssq += v.x * v.x + v.y * v.y + v.z * v.z + v.w * v.w;
        }
        #pragma unroll
        for (int o = 16; o > 0; o >>= 1)
            ssq += __shfl_xor_sync(0xffffffffu, ssq, o);
        if (lane == 0)
            inv_s[wid] = 1.0f / fmaxf(sqrtf(ssq), EPS);
    }
    __syncthreads();   // tile + inv_s[0..19] visible

    // ---- Phase B: thread t (<512) owns d = t; single smem pass ----
    float avg = 0.f, zn = 0.f;
    if (t < DD) {
        #pragma unroll
        for (int p = 0; p < PP; ++p) {
            float v = tilef[p * ROWF + t];   // consecutive t -> conflict-free
            avg += v;
            zn  += v * inv_s[p];             // broadcast read
        }
        avg *= (1.0f / (float)PP);

        // ||avg||^2 block reduction (warps 0..15)
        float a2 = avg * avg;
        #pragma unroll
        for (int o = 16; o > 0; o >>= 1)
            a2 += __shfl_xor_sync(0xffffffffu, a2, o);
        if (lane == 0) wp[wid] = a2;
    }
    __syncthreads();
    if (t == 0) {
        float v = 0.f;
        #pragma unroll
        for (int w = 0; w < NWARP_R; ++w) v += wp[w];
        inv_s[20] = 1.0f / fmaxf(sqrtf(v), EPS);
    }
    __syncthreads();

    if (t < DD) {
        const float an = avg * inv_s[20];

        // diag partial: zn * an, block-reduced over warps 0..15
        float dsum = zn * an;
        #pragma unroll
        for (int o = 16; o > 0; o >>= 1)
            dsum += __shfl_xor_sync(0xffffffffu, dsum, o);
        if (lane == 0) wdg[wid] = dsum;

        // slotted global accumulation (128 updates per address, coalesced)
        atomicAdd(&gS[slot][t], an);
        atomicAdd(&gT[slot][t], zn);
    }
    __syncthreads();
    if (t == 0) {
        float dg = 0.f;
        #pragma unroll
        for (int w = 0; w < NWARP_R; ++w) dg += wdg[w];
        atomicAdd(&gDiag[slot], dg);
    }

    // ---- completion ticket (threadFenceReduction pattern) ----
    __threadfence();
    __syncthreads();
    if (t == 0) ticket_s = atomicAdd(&gTicket, 1u);
    __syncthreads();
    if (ticket_s != NN - 1) return;

    // ======== LAST BLOCK (runs once): final scalar + state reset ========
    if (t < DD) {
        float S = 0.f, T = 0.f;
        #pragma unroll 1
        for (int sl = 0; sl < NS; ++sl) { S += gS[sl][t]; T += gT[sl][t]; }
        float v = S * T;
        #pragma unroll
        for (int o = 16; o > 0; o >>= 1)
            v += __shfl_xor_sync(0xffffffffu, v, o);
        if (lane == 0) wdg[wid] = v;       // reuse wdg for T.S partials
    }
    __syncthreads();

    if (t == 0) {
        float ts = 0.f;
        #pragma unroll
        for (int w = 0; w < NWARP_R; ++w) ts += wdg[w];
        float dg_all = 0.f;
        #pragma unroll 1
        for (int sl = 0; sl < NS; ++sl) dg_all += gDiag[sl];
        const double count = 20.0 * 1024.0 * 1023.0;
        out[0] = (float)(((double)ts - (double)dg_all) / count - 1.0);
    }

    // re-zero persistent state for the next graph replay
    if (t < DD) {
        #pragma unroll 1
        for (int sl = 0; sl < NS; ++sl) { gS[sl][t] = 0.f; gT[sl][t] = 0.f; }
    }
    if (t < NS) gDiag[t] = 0.f;
    if (t == 0) gTicket = 0u;
}

extern "C" void kernel_launch(void* const* d_in, const int* in_sizes, int n_in,
                              void* d_out, int out_size) {
    const float* z_list = (const float*)d_in[0];
    // d_in[1] (z_avg) ignored — reference recomputes it from z_list.
    (void)in_sizes; (void)n_in; (void)out_size;
    float* out = (float*)d_out;

    fused_kernel<<<NN, TPB>>>(z_list, out);
}